// round 12
// baseline (speedup 1.0000x reference)
#include <cuda_runtime.h>
#include <cuda_fp16.h>

// Fused MultiAttention: QKV proj + causal softmax attention + FC.
// B=32768, T=8, D=256, H=4, DH=64.  fp16 mma.sync, fp32 accumulate.
// CTA = 256 threads (8 warps), 128 rows (16 batches); warp = 16 rows = 2 batches.

#define NH      4
#define DMODEL  256
#define MT      128
#define XS      264   // x smem row stride in halves (528 B, 16B-aligned, conflict-free)
#define KV      72    // k/v smem row stride in halves (144 B)
#define SMEM_BYTES 137216

// Weights in mma-B-fragment layout (built by prep_kernel each launch).
// QKV: [h][nt(8)][kt(16)][lane(32)]  uint2 {pack(Wk,Wk1), pack(Wk8,Wk9)}
// FC:  [h][nt(32)][kt(4)][lane(32)]
static __device__ __align__(16) uint2 g_wq[16384];
static __device__ __align__(16) uint2 g_wk[16384];
static __device__ __align__(16) uint2 g_wv[16384];
static __device__ __align__(16) uint2 g_wfc[16384];

__device__ __forceinline__ unsigned pack2(float a, float b) {
    __half2 h = __floats2half2_rn(a, b);
    return *reinterpret_cast<unsigned*>(&h);
}

__device__ __forceinline__ void ldm4(unsigned r[4], const void* p) {
    unsigned a = (unsigned)__cvta_generic_to_shared(p);
    asm volatile("ldmatrix.sync.aligned.m8n8.x4.shared.b16 {%0,%1,%2,%3}, [%4];"
                 : "=r"(r[0]), "=r"(r[1]), "=r"(r[2]), "=r"(r[3]) : "r"(a));
}

__device__ __forceinline__ void ldm4t(unsigned r[4], const void* p) {
    unsigned a = (unsigned)__cvta_generic_to_shared(p);
    asm volatile("ldmatrix.sync.aligned.m8n8.x4.trans.shared.b16 {%0,%1,%2,%3}, [%4];"
                 : "=r"(r[0]), "=r"(r[1]), "=r"(r[2]), "=r"(r[3]) : "r"(a));
}

__device__ __forceinline__ void mma16816(float c[4], const unsigned a[4],
                                         unsigned b0, unsigned b1) {
    asm volatile("mma.sync.aligned.m16n8k16.row.col.f32.f16.f16.f32 "
                 "{%0,%1,%2,%3}, {%4,%5,%6,%7}, {%8,%9}, {%0,%1,%2,%3};"
                 : "+f"(c[0]), "+f"(c[1]), "+f"(c[2]), "+f"(c[3])
                 : "r"(a[0]), "r"(a[1]), "r"(a[2]), "r"(a[3]), "r"(b0), "r"(b1));
}

// ---------------- weight prep: fp32 -> fp16 B-fragment layout ----------------
__global__ void prep_kernel(const float* __restrict__ Wq, const float* __restrict__ Wk,
                            const float* __restrict__ Wv, const float* __restrict__ Wfc) {
    int t = blockIdx.x * 256 + threadIdx.x;   // 0..16383
    int lane   = t & 31;
    int n_half = lane >> 2;                   // B-frag col within n-tile
    int k_off  = (lane & 3) << 1;             // B-frag k base

    // QKV: t = h*4096 + nt*512 + kt*32 + lane
    {
        int h  = t >> 12;
        int nt = (t >> 9) & 7;
        int kt = (t >> 5) & 15;
        int n  = nt * 8 + n_half;             // 0..63 within head
        int k  = kt * 16 + k_off;             // 0..255
        const float* W3[3] = {Wq, Wk, Wv};
        uint2* G3[3] = {g_wq, g_wk, g_wv};
        #pragma unroll
        for (int w = 0; w < 3; ++w) {
            const float* base = W3[w] + (size_t)h * (DMODEL * 64) + n;
            uint2 o;
            o.x = pack2(base[(size_t)k * 64],       base[(size_t)(k + 1) * 64]);
            o.y = pack2(base[(size_t)(k + 8) * 64], base[(size_t)(k + 9) * 64]);
            G3[w][t] = o;
        }
    }
    // FC: t = h*4096 + nt*128 + kt*32 + lane
    {
        int h  = t >> 12;
        int nt = (t >> 7) & 31;
        int kt = (t >> 5) & 3;
        int n  = nt * 8 + n_half;             // 0..255
        int k  = h * 64 + kt * 16 + k_off;    // 0..255 (head-chunk of DHEAD)
        uint2 o;
        o.x = pack2(Wfc[(size_t)k * 256 + n],       Wfc[(size_t)(k + 1) * 256 + n]);
        o.y = pack2(Wfc[(size_t)(k + 8) * 256 + n], Wfc[(size_t)(k + 9) * 256 + n]);
        g_wfc[t] = o;
    }
}

// ---------------- helpers ----------------
__device__ __forceinline__ void stage(uint2* ws, const uint2* src) {
    __syncthreads();                          // protect previous ws consumers
    uint4* d = reinterpret_cast<uint4*>(ws);
    const uint4* s = reinterpret_cast<const uint4*>(src);
    for (int i = threadIdx.x; i < 2048; i += 256) d[i] = s[i];
    __syncthreads();
}

// [16,256] @ [256,64] per warp -> acc[8 ntiles][4]
__device__ __forceinline__ void gemm_proj(float acc[8][4], const __half* arow,
                                          const uint2* ws, int lane) {
    #pragma unroll
    for (int i = 0; i < 8; ++i)
        acc[i][0] = acc[i][1] = acc[i][2] = acc[i][3] = 0.f;
    #pragma unroll 4
    for (int kt = 0; kt < 16; ++kt) {
        unsigned a[4];
        ldm4(a, arow + kt * 16);
        const uint2* wp = ws + kt * 32 + lane;
        #pragma unroll
        for (int nt = 0; nt < 8; ++nt) {
            uint2 b = wp[nt * 512];
            mma16816(acc[nt], a, b.x, b.y);
        }
    }
}

__device__ __forceinline__ void store_kv(__half* dst, const float acc[8][4],
                                         const float* __restrict__ bias,
                                         int row0, int g, int m2) {
    #pragma unroll
    for (int nt = 0; nt < 8; ++nt) {
        int c = nt * 8 + m2;
        float2 bb = *reinterpret_cast<const float2*>(bias + c);
        *reinterpret_cast<__half2*>(dst + (row0 + g) * KV + c) =
            __floats2half2_rn(acc[nt][0] + bb.x, acc[nt][1] + bb.y);
        *reinterpret_cast<__half2*>(dst + (row0 + g + 8) * KV + c) =
            __floats2half2_rn(acc[nt][2] + bb.x, acc[nt][3] + bb.y);
    }
    __syncwarp();
}

// causal softmax over one 8-wide row held as 2 values/lane across a lane-quad
__device__ __forceinline__ void softmax2(float s0, float s1, int t, int j0,
                                         float& p0, float& p1) {
    float v0 = (j0     <= t) ? s0 : -1e30f;
    float v1 = (j0 + 1 <= t) ? s1 : -1e30f;
    float m = fmaxf(v0, v1);
    m = fmaxf(m, __shfl_xor_sync(0xffffffffu, m, 1));
    m = fmaxf(m, __shfl_xor_sync(0xffffffffu, m, 2));
    float e0 = (j0     <= t) ? __expf(v0 - m) : 0.f;
    float e1 = (j0 + 1 <= t) ? __expf(v1 - m) : 0.f;
    float s = e0 + e1;
    s += __shfl_xor_sync(0xffffffffu, s, 1);
    s += __shfl_xor_sync(0xffffffffu, s, 2);
    float r = 1.f / s;
    p0 = e0 * r;
    p1 = e1 * r;
}

// ---------------- main fused kernel ----------------
__global__ void __launch_bounds__(256, 1)
attn_kernel(const float* __restrict__ x,
            const float* __restrict__ bq, const float* __restrict__ bk,
            const float* __restrict__ bv, const float* __restrict__ bfc,
            float* __restrict__ out)
{
    extern __shared__ char smem[];
    __half* xs = reinterpret_cast<__half*>(smem);            // [128][264]  67584 B
    uint2*  ws = reinterpret_cast<uint2*>(smem + 67584);     // 4096 uint2  32768 B
    __half* ks = reinterpret_cast<__half*>(smem + 100352);   // [128][72]   18432 B
    __half* vs = reinterpret_cast<__half*>(smem + 118784);   // [128][72]   18432 B

    const int tid  = threadIdx.x;
    const int lane = tid & 31;
    const int warp = tid >> 5;
    const int g    = lane >> 2;          // row-in-8-group
    const int m2   = (lane & 3) << 1;    // col-pair base
    const int row0 = warp << 4;          // warp's 16-row window in the CTA tile
    const size_t m0 = (size_t)blockIdx.x * MT;

    // x tile -> fp16 smem
    {
        const float4* xg = reinterpret_cast<const float4*>(x + m0 * DMODEL);
        for (int i = tid; i < MT * 64; i += 256) {
            float4 v = xg[i];
            __half2* d = reinterpret_cast<__half2*>(xs + (i >> 6) * XS + (i & 63) * 4);
            d[0] = __floats2half2_rn(v.x, v.y);
            d[1] = __floats2half2_rn(v.z, v.w);
        }
    }
    // first stage() below syncs before xs is read

    float facc[32][4];                   // FC accumulator: 16 rows x 256 cols / warp
    #pragma unroll
    for (int i = 0; i < 32; ++i)
        facc[i][0] = facc[i][1] = facc[i][2] = facc[i][3] = 0.f;

    const __half* arow = xs + (row0 + (lane & 15)) * XS + ((lane >> 4) << 3);
    const __half* krow = ks + (row0 + (lane & 15)) * KV + ((lane >> 4) << 3);
    const __half* vrow = vs + (row0 + (lane & 15)) * KV + ((lane >> 4) << 3);

    #pragma unroll 1
    for (int h = 0; h < NH; ++h) {
        unsigned qf[4][4];   // Q as A-fragments (4 k16-tiles over DH=64), pre-scaled

        // ---- Q = (x @ Wq_h + bq) / 8, kept in registers ----
        stage(ws, g_wq + h * 4096);
        {
            float acc[8][4];
            gemm_proj(acc, arow, ws, lane);
            #pragma unroll
            for (int nt = 0; nt < 8; ++nt) {
                float2 bb = *reinterpret_cast<const float2*>(bq + h * 64 + nt * 8 + m2);
                acc[nt][0] = (acc[nt][0] + bb.x) * 0.125f;
                acc[nt][1] = (acc[nt][1] + bb.y) * 0.125f;
                acc[nt][2] = (acc[nt][2] + bb.x) * 0.125f;
                acc[nt][3] = (acc[nt][3] + bb.y) * 0.125f;
            }
            #pragma unroll
            for (int kt = 0; kt < 4; ++kt) {   // C-frag -> A-frag reinterpret
                qf[kt][0] = pack2(acc[2*kt][0],     acc[2*kt][1]);
                qf[kt][1] = pack2(acc[2*kt][2],     acc[2*kt][3]);
                qf[kt][2] = pack2(acc[2*kt + 1][0], acc[2*kt + 1][1]);
                qf[kt][3] = pack2(acc[2*kt + 1][2], acc[2*kt + 1][3]);
            }
        }
        // ---- K -> smem ----
        stage(ws, g_wk + h * 4096);
        {
            float acc[8][4];
            gemm_proj(acc, arow, ws, lane);
            store_kv(ks, acc, bk + h * 64, row0, g, m2);
        }
        // ---- V -> smem ----
        stage(ws, g_wv + h * 4096);
        {
            float acc[8][4];
            gemm_proj(acc, arow, ws, lane);
            store_kv(vs, acc, bv + h * 64, row0, g, m2);
        }
        // ---- FC weight chunk for this head (syncthreads also publishes ks/vs) ----
        stage(ws, g_wfc + h * 4096);

        // ---- S = Q K^T (warp-local; rows 0-7 = batch0, 8-15 = batch1) ----
        float sa[2][4];
        sa[0][0] = sa[0][1] = sa[0][2] = sa[0][3] = 0.f;
        sa[1][0] = sa[1][1] = sa[1][2] = sa[1][3] = 0.f;
        #pragma unroll
        for (int kt = 0; kt < 4; ++kt) {
            unsigned kb[4];
            ldm4(kb, krow + kt * 16);                 // K rows as S B-frags
            mma16816(sa[0], qf[kt], kb[0], kb[2]);    // kv rows 0-7
            mma16816(sa[1], qf[kt], kb[1], kb[3]);    // kv rows 8-15
        }
        // ---- causal softmax -> P as A-fragments (block-diagonal) ----
        unsigned pf[4];
        {
            float p00, p01, p10, p11;
            softmax2(sa[0][0], sa[0][1], g, m2, p00, p01);  // batch0 row g
            softmax2(sa[1][2], sa[1][3], g, m2, p10, p11);  // batch1 row g
            pf[0] = pack2(p00, p01);   // (row g,  kv 0-7)
            pf[1] = 0u;                // cross-batch zero
            pf[2] = 0u;
            pf[3] = pack2(p10, p11);   // (row g+8, kv 8-15)
        }
        // ---- O = P @ V (16x64) in registers ----
        float oa[8][4];
        #pragma unroll
        for (int i = 0; i < 8; ++i)
            oa[i][0] = oa[i][1] = oa[i][2] = oa[i][3] = 0.f;
        #pragma unroll
        for (int i2 = 0; i2 < 4; ++i2) {
            unsigned vb[4];
            ldm4t(vb, vrow + i2 * 16);                // V cols as PV B-frags
            mma16816(oa[2*i2],     pf, vb[0], vb[1]);
            mma16816(oa[2*i2 + 1], pf, vb[2], vb[3]);
        }
        // ---- FC accumulate: facc += O_h @ Wfc[h*64:(h+1)*64, :] ----
        #pragma unroll
        for (int kt = 0; kt < 4; ++kt) {
            unsigned fa[4];                            // C-frag -> A-frag
            fa[0] = pack2(oa[2*kt][0],     oa[2*kt][1]);
            fa[1] = pack2(oa[2*kt][2],     oa[2*kt][3]);
            fa[2] = pack2(oa[2*kt + 1][0], oa[2*kt + 1][1]);
            fa[3] = pack2(oa[2*kt + 1][2], oa[2*kt + 1][3]);
            const uint2* wp = ws + kt * 32 + lane;
            #pragma unroll
            for (int nt = 0; nt < 32; ++nt) {
                uint2 b = wp[nt * 128];
                mma16816(facc[nt], fa, b.x, b.y);
            }
        }
    }

    // ---- epilogue: out = facc + bfc ----
    float* o0 = out + (m0 + row0 + g) * DMODEL;
    float* o1 = out + (m0 + row0 + g + 8) * DMODEL;
    #pragma unroll
    for (int nt = 0; nt < 32; ++nt) {
        int c = nt * 8 + m2;
        float2 bb = *reinterpret_cast<const float2*>(bfc + c);
        *reinterpret_cast<float2*>(o0 + c) = make_float2(facc[nt][0] + bb.x, facc[nt][1] + bb.y);
        *reinterpret_cast<float2*>(o1 + c) = make_float2(facc[nt][2] + bb.x, facc[nt][3] + bb.y);
    }
}

extern "C" void kernel_launch(void* const* d_in, const int* in_sizes, int n_in,
                              void* d_out, int out_size) {
    const float* x   = (const float*)d_in[0];
    const float* Wq  = (const float*)d_in[1];
    const float* bq  = (const float*)d_in[2];
    const float* Wk  = (const float*)d_in[3];
    const float* bk  = (const float*)d_in[4];
    const float* Wv  = (const float*)d_in[5];
    const float* bv  = (const float*)d_in[6];
    const float* Wfc = (const float*)d_in[7];
    const float* bfc = (const float*)d_in[8];
    float* out = (float*)d_out;

    cudaFuncSetAttribute(attn_kernel, cudaFuncAttributeMaxDynamicSharedMemorySize, SMEM_BYTES);

    int rows = in_sizes[0] / DMODEL;     // B * T
    int grid = rows / MT;                // 2048

    prep_kernel<<<64, 256>>>(Wq, Wk, Wv, Wfc);
    attn_kernel<<<grid, 256, SMEM_BYTES>>>(x, bq, bk, bv, bfc, out);
}